// round 1
// baseline (speedup 1.0000x reference)
#include <cuda_runtime.h>
#include <cuda_bf16.h>
#include <cstdint>

// Problem constants
#define BATCH 4
#define SEQ   2048
#define DMODEL 1024
#define NHEAD 16
#define HDIM  64
#define MROWS (BATCH*SEQ)         // 8192

// ---------------- scratch (device globals; no allocation allowed) ----------
__device__ float g_qh[(size_t)BATCH*NHEAD*SEQ*HDIM];   // (b,h,s,hd)
__device__ float g_kh[(size_t)BATCH*NHEAD*SEQ*HDIM];
__device__ float g_vh[(size_t)BATCH*NHEAD*SEQ*HDIM];
__device__ float g_ob[(size_t)BATCH*SEQ*DMODEL];       // attention out, (b,s,d)
__device__ unsigned char g_mask[BATCH*SEQ];
__device__ int g_mode;

#define NEG_INF __int_as_float(0xff800000)

// ---------------- mask dtype detection + canonicalization ------------------
// q_mask is boolean; serialized dtype unknown (u8 / i32 / f32). Detect from
// byte patterns within the first 8192 bytes (minimum possible buffer size):
//   u8 : bytes at pos%4==1 are ~90% nonzero
//   i32: bytes at pos%4!=0 all zero
//   f32: bytes at pos%4==3 are 0x3f for 1.0f
__global__ void detect_mask_kernel(const unsigned char* __restrict__ p) {
    __shared__ int s1, s3;
    if (threadIdx.x == 0) { s1 = 0; s3 = 0; }
    __syncthreads();
    int l1 = 0, l3 = 0;
    for (int i = threadIdx.x; i < BATCH*SEQ; i += blockDim.x) {
        unsigned char v = p[i];
        int m = i & 3;
        if (m == 1 && v) l1 = 1;
        if (m == 3 && v) l3 = 1;
    }
    if (l1) atomicOr(&s1, 1);
    if (l3) atomicOr(&s3, 1);
    __syncthreads();
    if (threadIdx.x == 0) g_mode = s1 ? 0 : (s3 ? 1 : 2);  // 0=u8, 1=f32, 2=i32
}

__global__ void convert_mask_kernel(const unsigned char* __restrict__ p) {
    int i = blockIdx.x * blockDim.x + threadIdx.x;
    if (i >= BATCH*SEQ) return;
    int mode = g_mode;
    unsigned char r;
    if (mode == 0)      r = (p[i] != 0);
    else if (mode == 1) r = (((const float*)p)[i] != 0.0f);
    else                r = (((const int*)p)[i] != 0);
    g_mask[i] = r;
}

// ---------------- GEMM: C = A @ W^T + bias ---------------------------------
// A: [M, K] row-major, W: [N, K] row-major (nn.Linear weight), M=8192, N=K=1024.
// BM=BN=64, BK=16, 256 threads, 4x4 micro-tile.
// SPLIT: scatter output to (b,h,s,hd) layout for attention consumption.
template <bool SPLIT>
__global__ void gemm_bias_kernel(const float* __restrict__ A,
                                 const float* __restrict__ W,
                                 const float* __restrict__ bias,
                                 float* __restrict__ C) {
    const int K = DMODEL;
    __shared__ float As[16][64];
    __shared__ float Ws[16][64];

    int tid = threadIdx.x;
    int ty = tid >> 4, tx = tid & 15;
    int m0 = blockIdx.y * 64, n0 = blockIdx.x * 64;

    int lr = tid >> 2;          // 0..63 (tile row for loading)
    int lk = (tid & 3) << 2;    // 0,4,8,12 (k offset, float4)
    const float* Ap = A + (size_t)(m0 + lr) * K + lk;
    const float* Wp = W + (size_t)(n0 + lr) * K + lk;

    float acc[4][4] = {};

    for (int k0 = 0; k0 < K; k0 += 16) {
        float4 av = *(const float4*)(Ap + k0);
        float4 wv = *(const float4*)(Wp + k0);
        __syncthreads();
        As[lk + 0][lr] = av.x; As[lk + 1][lr] = av.y;
        As[lk + 2][lr] = av.z; As[lk + 3][lr] = av.w;
        Ws[lk + 0][lr] = wv.x; Ws[lk + 1][lr] = wv.y;
        Ws[lk + 2][lr] = wv.z; Ws[lk + 3][lr] = wv.w;
        __syncthreads();

        #pragma unroll
        for (int kk = 0; kk < 16; kk++) {
            float a[4], w[4];
            #pragma unroll
            for (int i = 0; i < 4; i++) a[i] = As[kk][ty * 4 + i];
            #pragma unroll
            for (int j = 0; j < 4; j++) w[j] = Ws[kk][tx * 4 + j];
            #pragma unroll
            for (int i = 0; i < 4; i++)
                #pragma unroll
                for (int j = 0; j < 4; j++)
                    acc[i][j] = fmaf(a[i], w[j], acc[i][j]);
        }
    }

    #pragma unroll
    for (int i = 0; i < 4; i++) {
        int m = m0 + ty * 4 + i;
        #pragma unroll
        for (int j = 0; j < 4; j++) {
            int n = n0 + tx * 4 + j;
            float v = acc[i][j] + bias[n];
            if (SPLIT) {
                int b = m >> 11, s = m & (SEQ - 1);
                int h = n >> 6, hd = n & (HDIM - 1);
                C[((((size_t)b * NHEAD + h) * SEQ) + s) * HDIM + hd] = v;
            } else {
                C[(size_t)m * DMODEL + n] = v;
            }
        }
    }
}

// ---------------- Flash attention ------------------------------------------
// Grid: (SEQ/64, BATCH*NHEAD). 256 threads. 64 queries x 64 keys per tile,
// HD=64. Online softmax with key mask; masked-query rows -> 0.
#define AP 65   // padded row stride in shared

__global__ void attn_kernel(const float* __restrict__ qh,
                            const float* __restrict__ kh,
                            const float* __restrict__ vh,
                            float* __restrict__ ob) {
    int qt = blockIdx.x;
    int bh = blockIdx.y;
    int b = bh >> 4, h = bh & 15;

    extern __shared__ float sm[];
    float* Qs = sm;
    float* Ks = Qs + 64 * AP;
    float* Vs = Ks + 64 * AP;
    float* Ss = Vs + 64 * AP;
    __shared__ float m_s[64], l_s[64], al_s[64], kmadd[64];
    __shared__ unsigned char qm_s[64];

    int tid = threadIdx.x;
    int ty = tid >> 4, tx = tid & 15;
    int q0 = qt * 64;

    const float* qb = qh + ((size_t)bh * SEQ + q0) * HDIM;
    const float* kb = kh + (size_t)bh * SEQ * HDIM;
    const float* vb = vh + (size_t)bh * SEQ * HDIM;

    // load Q tile (64x64)
    for (int f = tid; f < 1024; f += 256) {
        int r = f >> 4, c = (f & 15) << 2;
        float4 v = *(const float4*)(qb + r * HDIM + c);
        Qs[r * AP + c + 0] = v.x; Qs[r * AP + c + 1] = v.y;
        Qs[r * AP + c + 2] = v.z; Qs[r * AP + c + 3] = v.w;
    }
    if (tid < 64) {
        qm_s[tid] = g_mask[b * SEQ + q0 + tid];
        m_s[tid] = NEG_INF;
        l_s[tid] = 0.0f;
    }

    float O[4][4] = {};

    for (int kt = 0; kt < SEQ / 64; kt++) {
        __syncthreads();   // prior iter done with Ks/Vs/Ss
        int k0 = kt * 64;
        for (int f = tid; f < 1024; f += 256) {
            int r = f >> 4, c = (f & 15) << 2;
            float4 kv = *(const float4*)(kb + (size_t)(k0 + r) * HDIM + c);
            float4 vv = *(const float4*)(vb + (size_t)(k0 + r) * HDIM + c);
            Ks[r * AP + c + 0] = kv.x; Ks[r * AP + c + 1] = kv.y;
            Ks[r * AP + c + 2] = kv.z; Ks[r * AP + c + 3] = kv.w;
            Vs[r * AP + c + 0] = vv.x; Vs[r * AP + c + 1] = vv.y;
            Vs[r * AP + c + 2] = vv.z; Vs[r * AP + c + 3] = vv.w;
        }
        if (tid < 64)
            kmadd[tid] = g_mask[b * SEQ + k0 + tid] ? 0.0f : NEG_INF;
        __syncthreads();

        // scores tile S = Q K^T
        float acc[4][4] = {};
        #pragma unroll 8
        for (int d = 0; d < HDIM; d++) {
            float a[4], w[4];
            #pragma unroll
            for (int i = 0; i < 4; i++) a[i] = Qs[(ty * 4 + i) * AP + d];
            #pragma unroll
            for (int j = 0; j < 4; j++) w[j] = Ks[(tx * 4 + j) * AP + d];
            #pragma unroll
            for (int i = 0; i < 4; i++)
                #pragma unroll
                for (int j = 0; j < 4; j++)
                    acc[i][j] = fmaf(a[i], w[j], acc[i][j]);
        }
        #pragma unroll
        for (int i = 0; i < 4; i++)
            #pragma unroll
            for (int j = 0; j < 4; j++)
                Ss[(ty * 4 + i) * AP + tx * 4 + j] =
                    acc[i][j] * 0.125f + kmadd[tx * 4 + j];
        __syncthreads();

        // online softmax row update: 4 threads per row
        {
            int row = tid >> 2, g = tid & 3;
            int cb = row * AP + g * 16;
            float tm = NEG_INF;
            #pragma unroll
            for (int c = 0; c < 16; c++) tm = fmaxf(tm, Ss[cb + c]);
            tm = fmaxf(tm, __shfl_xor_sync(0xffffffffu, tm, 1));
            tm = fmaxf(tm, __shfl_xor_sync(0xffffffffu, tm, 2));
            float mold = m_s[row];
            float mnew = fmaxf(mold, tm);
            float rs = 0.0f, alpha;
            if (mnew == NEG_INF) {
                alpha = 1.0f;
                #pragma unroll
                for (int c = 0; c < 16; c++) Ss[cb + c] = 0.0f;
            } else {
                alpha = __expf(mold - mnew);   // mold=-inf -> 0
                #pragma unroll
                for (int c = 0; c < 16; c++) {
                    float p = __expf(Ss[cb + c] - mnew);  // -inf -> 0
                    Ss[cb + c] = p;
                    rs += p;
                }
            }
            rs += __shfl_xor_sync(0xffffffffu, rs, 1);
            rs += __shfl_xor_sync(0xffffffffu, rs, 2);
            if (g == 0) {
                m_s[row] = mnew;
                l_s[row] = l_s[row] * alpha + rs;
                al_s[row] = alpha;
            }
        }
        __syncthreads();

        // O = O*alpha + P @ V
        float al[4];
        #pragma unroll
        for (int i = 0; i < 4; i++) al[i] = al_s[ty * 4 + i];
        #pragma unroll
        for (int i = 0; i < 4; i++)
            #pragma unroll
            for (int j = 0; j < 4; j++) O[i][j] *= al[i];
        #pragma unroll 8
        for (int kk = 0; kk < 64; kk++) {
            float p[4], v[4];
            #pragma unroll
            for (int i = 0; i < 4; i++) p[i] = Ss[(ty * 4 + i) * AP + kk];
            #pragma unroll
            for (int j = 0; j < 4; j++) v[j] = Vs[kk * AP + tx * 4 + j];
            #pragma unroll
            for (int i = 0; i < 4; i++)
                #pragma unroll
                for (int j = 0; j < 4; j++)
                    O[i][j] = fmaf(p[i], v[j], O[i][j]);
        }
    }

    // epilogue: divide by l, zero masked query rows, write (b,s,d)
    #pragma unroll
    for (int i = 0; i < 4; i++) {
        int r = ty * 4 + i;
        float sc = qm_s[r] ? (1.0f / l_s[r]) : 0.0f;
        size_t base = ((size_t)b * SEQ + q0 + r) * DMODEL + h * HDIM + tx * 4;
        float4 v;
        v.x = O[i][0] * sc; v.y = O[i][1] * sc;
        v.z = O[i][2] * sc; v.w = O[i][3] * sc;
        *(float4*)(ob + base) = v;
    }
}

// ---------------- launch ----------------------------------------------------
extern "C" void kernel_launch(void* const* d_in, const int* in_sizes, int n_in,
                              void* d_out, int out_size) {
    const float* q    = (const float*)d_in[0];
    const unsigned char* mask = (const unsigned char*)d_in[1];
    const float* Wq   = (const float*)d_in[2];
    const float* bq   = (const float*)d_in[3];
    const float* Wk   = (const float*)d_in[4];
    const float* bk   = (const float*)d_in[5];
    const float* Wv   = (const float*)d_in[6];
    const float* bv   = (const float*)d_in[7];
    const float* Wo   = (const float*)d_in[8];
    const float* bo   = (const float*)d_in[9];
    float* out = (float*)d_out;

    float *qh, *kh, *vh, *obuf;
    cudaGetSymbolAddress((void**)&qh, g_qh);
    cudaGetSymbolAddress((void**)&kh, g_kh);
    cudaGetSymbolAddress((void**)&vh, g_vh);
    cudaGetSymbolAddress((void**)&obuf, g_ob);

    detect_mask_kernel<<<1, 256>>>(mask);
    convert_mask_kernel<<<(BATCH*SEQ + 255) / 256, 256>>>(mask);

    dim3 gg(DMODEL / 64, MROWS / 64);   // (16, 128)
    gemm_bias_kernel<true><<<gg, 256>>>(q, Wq, bq, qh);
    gemm_bias_kernel<true><<<gg, 256>>>(q, Wk, bk, kh);
    gemm_bias_kernel<true><<<gg, 256>>>(q, Wv, bv, vh);

    int smem = 4 * 64 * AP * (int)sizeof(float);   // 66560 B
    cudaFuncSetAttribute(attn_kernel,
                         cudaFuncAttributeMaxDynamicSharedMemorySize, smem);
    attn_kernel<<<dim3(SEQ / 64, BATCH * NHEAD), 256, smem>>>(qh, kh, vh, obuf);

    gemm_bias_kernel<false><<<gg, 256>>>(obuf, Wo, bo, out);
}

// round 2
// speedup vs baseline: 2.2897x; 2.2897x over previous
#include <cuda_runtime.h>
#include <cuda_bf16.h>
#include <cstdint>

// Problem constants
#define BATCH 4
#define SEQ   2048
#define DMODEL 1024
#define NHEAD 16
#define HDIM  64
#define MROWS (BATCH*SEQ)         // 8192

#define NEG_INF __int_as_float(0xff800000)

// ---------------- scratch (device globals; no allocation allowed) ----------
__device__ float g_qh[(size_t)BATCH*NHEAD*SEQ*HDIM];   // (b,h,s,hd)
__device__ float g_kh[(size_t)BATCH*NHEAD*SEQ*HDIM];
__device__ float g_vh[(size_t)BATCH*NHEAD*SEQ*HDIM];
__device__ float g_ob[(size_t)BATCH*SEQ*DMODEL];       // attention out, (b,s,d)
__device__ unsigned char g_mask[BATCH*SEQ];
__device__ int g_mode;

// ---------------- mask dtype detection + canonicalization ------------------
__global__ void detect_mask_kernel(const unsigned char* __restrict__ p) {
    __shared__ int s1, s3;
    if (threadIdx.x == 0) { s1 = 0; s3 = 0; }
    __syncthreads();
    int l1 = 0, l3 = 0;
    for (int i = threadIdx.x; i < BATCH*SEQ; i += blockDim.x) {
        unsigned char v = p[i];
        int m = i & 3;
        if (m == 1 && v) l1 = 1;
        if (m == 3 && v) l3 = 1;
    }
    if (l1) atomicOr(&s1, 1);
    if (l3) atomicOr(&s3, 1);
    __syncthreads();
    if (threadIdx.x == 0) g_mode = s1 ? 0 : (s3 ? 1 : 2);  // 0=u8, 1=f32, 2=i32
}

__global__ void convert_mask_kernel(const unsigned char* __restrict__ p) {
    int i = blockIdx.x * blockDim.x + threadIdx.x;
    if (i >= BATCH*SEQ) return;
    int mode = g_mode;
    unsigned char r;
    if (mode == 0)      r = (p[i] != 0);
    else if (mode == 1) r = (((const float*)p)[i] != 0.0f);
    else                r = (((const int*)p)[i] != 0);
    g_mask[i] = r;
}

// ---------------- mma / ldmatrix primitives ---------------------------------
__device__ __forceinline__ void mma16816(float* c, const uint32_t* a, const uint32_t* b) {
    asm volatile(
        "mma.sync.aligned.m16n8k16.row.col.f32.bf16.bf16.f32 "
        "{%0,%1,%2,%3}, {%4,%5,%6,%7}, {%8,%9}, {%0,%1,%2,%3};"
        : "+f"(c[0]), "+f"(c[1]), "+f"(c[2]), "+f"(c[3])
        : "r"(a[0]), "r"(a[1]), "r"(a[2]), "r"(a[3]), "r"(b[0]), "r"(b[1]));
}

__device__ __forceinline__ void ldm_x4(uint32_t* r, uint32_t addr) {
    asm volatile("ldmatrix.sync.aligned.m8n8.x4.shared.b16 {%0,%1,%2,%3}, [%4];"
                 : "=r"(r[0]), "=r"(r[1]), "=r"(r[2]), "=r"(r[3]) : "r"(addr));
}
__device__ __forceinline__ void ldm_x2(uint32_t* r, uint32_t addr) {
    asm volatile("ldmatrix.sync.aligned.m8n8.x2.shared.b16 {%0,%1}, [%2];"
                 : "=r"(r[0]), "=r"(r[1]) : "r"(addr));
}
__device__ __forceinline__ void ldm_x2t(uint32_t* r, uint32_t addr) {
    asm volatile("ldmatrix.sync.aligned.m8n8.x2.trans.shared.b16 {%0,%1}, [%2];"
                 : "=r"(r[0]), "=r"(r[1]) : "r"(addr));
}

// fp32 -> bf16 hi/lo split, 4 elems, store as 2x bfloat162
__device__ __forceinline__ void sts_hl4(__nv_bfloat16* H, __nv_bfloat16* L,
                                        int idx, float4 v) {
    float f[4] = {v.x, v.y, v.z, v.w};
    #pragma unroll
    for (int p = 0; p < 2; ++p) {
        __nv_bfloat16 h0 = __float2bfloat16(f[2*p]);
        __nv_bfloat16 h1 = __float2bfloat16(f[2*p+1]);
        __nv_bfloat16 l0 = __float2bfloat16(f[2*p]   - __bfloat162float(h0));
        __nv_bfloat16 l1 = __float2bfloat16(f[2*p+1] - __bfloat162float(h1));
        __nv_bfloat162 h2; h2.x = h0; h2.y = h1;
        __nv_bfloat162 l2; l2.x = l0; l2.y = l1;
        *(__nv_bfloat162*)(H + idx + 2*p) = h2;
        *(__nv_bfloat162*)(L + idx + 2*p) = l2;
    }
}

// ---------------- GEMM: C = A @ W^T + bias (bf16x3 tensor-core) -------------
// A: [M,K] f32 row-major; W: [N,K] f32 row-major. BM=BN=128, BK=32.
// 256 threads = 8 warps (2x4), warp tile 64x32, m16n8k16 fragments.
#define GST 40   // smem row stride (bf16 elems): 32 data + 8 pad (ldmatrix conflict-free)

template <bool SPLIT>
__global__ __launch_bounds__(256, 1) void gemm3_kernel(const float* __restrict__ A,
                                                       const float* __restrict__ W,
                                                       const float* __restrict__ bias,
                                                       float* __restrict__ C) {
    const int K = DMODEL;
    extern __shared__ __align__(16) unsigned char smraw[];
    __nv_bfloat16* Ah = (__nv_bfloat16*)smraw;
    __nv_bfloat16* Al = Ah + 128*GST;
    __nv_bfloat16* Bh = Al + 128*GST;
    __nv_bfloat16* Bl = Bh + 128*GST;

    int t = threadIdx.x;
    int lane = t & 31, warp = t >> 5;
    int wm = warp >> 2, wn = warp & 3;
    int m0 = blockIdx.y * 128, n0 = blockIdx.x * 128;

    int lrow = t >> 1;
    int lcol = (t & 1) * 16;
    const float4* Ag = (const float4*)(A + (size_t)(m0 + lrow) * K + lcol);
    const float4* Wg = (const float4*)(W + (size_t)(n0 + lrow) * K + lcol);

    uint32_t sb  = (uint32_t)__cvta_generic_to_shared(smraw);
    const uint32_t AhB = sb;
    const uint32_t AlB = sb + 128*GST*2;
    const uint32_t BhB = sb + 2*128*GST*2;
    const uint32_t BlB = sb + 3*128*GST*2;
    uint32_t aoff = ((lane & 15) * GST + ((lane >> 4) << 3)) * 2;
    uint32_t boff = ((lane & 7) * GST + (((lane >> 3) & 1) << 3)) * 2;

    float c[4][4][4] = {};
    float4 ra[4], rb[4];
    #pragma unroll
    for (int j = 0; j < 4; ++j) { ra[j] = Ag[j]; rb[j] = Wg[j]; }

    const int NIT = K / 32;   // 32
    for (int it = 0; it < NIT; ++it) {
        int sidx = lrow * GST + lcol;
        #pragma unroll
        for (int j = 0; j < 4; ++j) {
            sts_hl4(Ah, Al, sidx + j*4, ra[j]);
            sts_hl4(Bh, Bl, sidx + j*4, rb[j]);
        }
        __syncthreads();
        if (it + 1 < NIT) {
            const float4* An = Ag + (it + 1) * 8;
            const float4* Wn = Wg + (it + 1) * 8;
            #pragma unroll
            for (int j = 0; j < 4; ++j) { ra[j] = An[j]; rb[j] = Wn[j]; }
        }
        #pragma unroll
        for (int ks = 0; ks < 2; ++ks) {
            uint32_t kbyte = (uint32_t)(ks * 16) * 2;
            uint32_t afh[4][4], afl[4][4];
            #pragma unroll
            for (int mi = 0; mi < 4; ++mi) {
                uint32_t base = (uint32_t)((wm*64 + mi*16) * GST) * 2 + kbyte + aoff;
                ldm_x4(afh[mi], AhB + base);
                ldm_x4(afl[mi], AlB + base);
            }
            uint32_t bfh[4][2], bfl[4][2];
            #pragma unroll
            for (int ni = 0; ni < 4; ++ni) {
                uint32_t base = (uint32_t)((wn*32 + ni*8) * GST) * 2 + kbyte + boff;
                ldm_x2(bfh[ni], BhB + base);
                ldm_x2(bfl[ni], BlB + base);
            }
            #pragma unroll
            for (int mi = 0; mi < 4; ++mi)
                #pragma unroll
                for (int ni = 0; ni < 4; ++ni) {
                    mma16816(c[mi][ni], afh[mi], bfh[ni]);
                    mma16816(c[mi][ni], afh[mi], bfl[ni]);
                    mma16816(c[mi][ni], afl[mi], bfh[ni]);
                }
        }
        __syncthreads();
    }

    // epilogue
    int g = lane >> 2, cq = (lane & 3) * 2;
    #pragma unroll
    for (int mi = 0; mi < 4; ++mi) {
        int r0 = m0 + wm*64 + mi*16 + g;
        int r1 = r0 + 8;
        #pragma unroll
        for (int ni = 0; ni < 4; ++ni) {
            int col = n0 + wn*32 + ni*8 + cq;
            float b0 = bias[col], b1 = bias[col + 1];
            float2 v0 = {c[mi][ni][0] + b0, c[mi][ni][1] + b1};
            float2 v1 = {c[mi][ni][2] + b0, c[mi][ni][3] + b1};
            if (SPLIT) {
                int hh = col >> 6, hd = col & 63;
                int bi0 = r0 >> 11, s0 = r0 & 2047;
                int bi1 = r1 >> 11, s1 = r1 & 2047;
                *(float2*)&C[((((size_t)bi0*NHEAD + hh)*SEQ) + s0)*HDIM + hd] = v0;
                *(float2*)&C[((((size_t)bi1*NHEAD + hh)*SEQ) + s1)*HDIM + hd] = v1;
            } else {
                *(float2*)&C[(size_t)r0*DMODEL + col] = v0;
                *(float2*)&C[(size_t)r1*DMODEL + col] = v1;
            }
        }
    }
}

// ---------------- Flash attention (bf16x3 tensor-core) ----------------------
// grid (SEQ/64, B*H), 128 threads (4 warps). Warp w owns query rows [w*16, w*16+16).
#define AST 72   // smem row stride (bf16): 64 data + 8 pad

__global__ __launch_bounds__(128, 1) void attn_mma_kernel(const float* __restrict__ qh,
                                                          const float* __restrict__ kh,
                                                          const float* __restrict__ vh,
                                                          float* __restrict__ ob) {
    extern __shared__ __align__(16) unsigned char smraw[];
    __nv_bfloat16* Ksh = (__nv_bfloat16*)smraw;    // 64*AST each
    __nv_bfloat16* Ksl = Ksh + 64*AST;
    __nv_bfloat16* Vsh = Ksl + 64*AST;
    __nv_bfloat16* Vsl = Vsh + 64*AST;
    __nv_bfloat16* Psh = Vsl + 64*AST;             // doubles as Q staging
    __nv_bfloat16* Psl = Psh + 64*AST;
    float* km = (float*)(Psl + 64*AST);            // 64 floats

    int t = threadIdx.x, lane = t & 31, w = t >> 5;
    int g = lane >> 2, cq = (lane & 3) * 2;
    int qt = blockIdx.x, bh = blockIdx.y;
    int b = bh >> 4, h = bh & 15;
    int q0 = qt * 64;
    const float* qb = qh + ((size_t)bh * SEQ + q0) * HDIM;
    const float* kb = kh + (size_t)bh * SEQ * HDIM;
    const float* vb = vh + (size_t)bh * SEQ * HDIM;
    const unsigned char* mb = g_mask + b * SEQ;

    uint32_t sbse = (uint32_t)__cvta_generic_to_shared(smraw);
    const uint32_t KshB = sbse;
    const uint32_t KslB = sbse + 1*64*AST*2;
    const uint32_t VshB = sbse + 2*64*AST*2;
    const uint32_t VslB = sbse + 3*64*AST*2;
    const uint32_t PshB = sbse + 4*64*AST*2;
    const uint32_t PslB = sbse + 5*64*AST*2;
    uint32_t aoff = ((lane & 15) * AST + ((lane >> 4) << 3)) * 2;
    uint32_t boff = ((lane & 7) * AST + (((lane >> 3) & 1) << 3)) * 2;
    uint32_t voff = ((lane & 15) * AST) * 2;

    int lrow = t >> 1, lcol0 = (t & 1) * 32;

    // stage Q (fp32 -> bf16 hi/lo) and load per-warp Q fragments (persist in regs)
    {
        const float4* Qg = (const float4*)(qb + lrow*HDIM + lcol0);
        int sidx = lrow*AST + lcol0;
        #pragma unroll
        for (int j = 0; j < 8; ++j) sts_hl4(Psh, Psl, sidx + j*4, Qg[j]);
    }
    __syncthreads();
    uint32_t qfh[4][4], qfl[4][4];
    #pragma unroll
    for (int kt = 0; kt < 4; ++kt) {
        uint32_t base = (uint32_t)(w*16*AST + kt*16)*2 + aoff;
        ldm_x4(qfh[kt], PshB + base);
        ldm_x4(qfl[kt], PslB + base);
    }

    float oc[8][4] = {};
    float m0r = NEG_INF, m1r = NEG_INF, l0r = 0.f, l1r = 0.f;

    for (int it = 0; it < SEQ/64; ++it) {
        __syncthreads();   // everyone done reading Ks/Vs/Ps from prev iter
        int k0 = it * 64;
        {
            const float4* Kg = (const float4*)(kb + (size_t)(k0 + lrow)*HDIM + lcol0);
            const float4* Vg = (const float4*)(vb + (size_t)(k0 + lrow)*HDIM + lcol0);
            int sidx = lrow*AST + lcol0;
            #pragma unroll
            for (int j = 0; j < 8; ++j) {
                sts_hl4(Ksh, Ksl, sidx + j*4, Kg[j]);
                sts_hl4(Vsh, Vsl, sidx + j*4, Vg[j]);
            }
        }
        if (t < 64) km[t] = mb[k0 + t] ? 0.0f : NEG_INF;
        __syncthreads();

        // S = Q K^T  (16 rows x 64 keys per warp)
        float sc[8][4] = {};
        #pragma unroll
        for (int nt = 0; nt < 8; ++nt) {
            #pragma unroll
            for (int kt = 0; kt < 4; ++kt) {
                uint32_t base = (uint32_t)(nt*8*AST + kt*16)*2 + boff;
                uint32_t b2h[2], b2l[2];
                ldm_x2(b2h, KshB + base);
                ldm_x2(b2l, KslB + base);
                mma16816(sc[nt], qfh[kt], b2h);
                mma16816(sc[nt], qfh[kt], b2l);
                mma16816(sc[nt], qfl[kt], b2h);
            }
        }

        // online softmax (rows g and g+8 of warp strip)
        float r0m = NEG_INF, r1m = NEG_INF;
        #pragma unroll
        for (int nt = 0; nt < 8; ++nt) {
            float a0 = km[nt*8 + cq], a1 = km[nt*8 + cq + 1];
            sc[nt][0] = sc[nt][0]*0.125f + a0;
            sc[nt][1] = sc[nt][1]*0.125f + a1;
            sc[nt][2] = sc[nt][2]*0.125f + a0;
            sc[nt][3] = sc[nt][3]*0.125f + a1;
            r0m = fmaxf(r0m, fmaxf(sc[nt][0], sc[nt][1]));
            r1m = fmaxf(r1m, fmaxf(sc[nt][2], sc[nt][3]));
        }
        r0m = fmaxf(r0m, __shfl_xor_sync(0xffffffffu, r0m, 1));
        r0m = fmaxf(r0m, __shfl_xor_sync(0xffffffffu, r0m, 2));
        r1m = fmaxf(r1m, __shfl_xor_sync(0xffffffffu, r1m, 1));
        r1m = fmaxf(r1m, __shfl_xor_sync(0xffffffffu, r1m, 2));
        float mn0 = fmaxf(m0r, r0m), mn1 = fmaxf(m1r, r1m);
        float ms0 = (mn0 == NEG_INF) ? 0.0f : mn0;
        float ms1 = (mn1 == NEG_INF) ? 0.0f : mn1;
        float al0 = __expf(m0r - ms0), al1 = __expf(m1r - ms1);  // -inf -> 0, no NaN
        m0r = mn0; m1r = mn1;

        float rs0 = 0.f, rs1 = 0.f;
        int pr0 = (w*16 + g) * AST, pr1 = (w*16 + g + 8) * AST;
        #pragma unroll
        for (int nt = 0; nt < 8; ++nt) {
            float p0 = __expf(sc[nt][0] - ms0), p1 = __expf(sc[nt][1] - ms0);
            float p2 = __expf(sc[nt][2] - ms1), p3 = __expf(sc[nt][3] - ms1);
            rs0 += p0 + p1; rs1 += p2 + p3;
            __nv_bfloat16 h0 = __float2bfloat16(p0), h1 = __float2bfloat16(p1);
            __nv_bfloat16 h2 = __float2bfloat16(p2), h3 = __float2bfloat16(p3);
            __nv_bfloat162 hv0; hv0.x = h0; hv0.y = h1;
            __nv_bfloat162 hv1; hv1.x = h2; hv1.y = h3;
            __nv_bfloat162 lv0, lv1;
            lv0.x = __float2bfloat16(p0 - __bfloat162float(h0));
            lv0.y = __float2bfloat16(p1 - __bfloat162float(h1));
            lv1.x = __float2bfloat16(p2 - __bfloat162float(h2));
            lv1.y = __float2bfloat16(p3 - __bfloat162float(h3));
            *(__nv_bfloat162*)(Psh + pr0 + nt*8 + cq) = hv0;
            *(__nv_bfloat162*)(Psh + pr1 + nt*8 + cq) = hv1;
            *(__nv_bfloat162*)(Psl + pr0 + nt*8 + cq) = lv0;
            *(__nv_bfloat162*)(Psl + pr1 + nt*8 + cq) = lv1;
        }
        rs0 += __shfl_xor_sync(0xffffffffu, rs0, 1);
        rs0 += __shfl_xor_sync(0xffffffffu, rs0, 2);
        rs1 += __shfl_xor_sync(0xffffffffu, rs1, 1);
        rs1 += __shfl_xor_sync(0xffffffffu, rs1, 2);
        l0r = l0r * al0 + rs0;
        l1r = l1r * al1 + rs1;
        #pragma unroll
        for (int nt = 0; nt < 8; ++nt) {
            oc[nt][0] *= al0; oc[nt][1] *= al0;
            oc[nt][2] *= al1; oc[nt][3] *= al1;
        }
        __syncwarp();   // P smem rows are warp-private; warp-level visibility

        // O += P V
        #pragma unroll
        for (int kt = 0; kt < 4; ++kt) {
            uint32_t pb = (uint32_t)(w*16*AST + kt*16)*2 + aoff;
            uint32_t pfh[4], pfl[4];
            ldm_x4(pfh, PshB + pb);
            ldm_x4(pfl, PslB + pb);
            #pragma unroll
            for (int nt = 0; nt < 8; ++nt) {
                uint32_t vb2 = (uint32_t)(kt*16*AST + nt*8)*2 + voff;
                uint32_t v2h[2], v2l[2];
                ldm_x2t(v2h, VshB + vb2);
                ldm_x2t(v2l, VslB + vb2);
                mma16816(oc[nt], pfh, v2h);
                mma16816(oc[nt], pfh, v2l);
                mma16816(oc[nt], pfl, v2h);
            }
        }
    }

    // epilogue: normalize, zero masked query rows, write (b,s,d)
    int r0 = w*16 + g, r1 = r0 + 8;
    float inv0 = (mb[q0 + r0] && l0r > 0.f) ? 1.0f / l0r : 0.0f;
    float inv1 = (mb[q0 + r1] && l1r > 0.f) ? 1.0f / l1r : 0.0f;
    size_t base0 = ((size_t)b*SEQ + q0 + r0)*DMODEL + h*HDIM;
    size_t base1 = ((size_t)b*SEQ + q0 + r1)*DMODEL + h*HDIM;
    #pragma unroll
    for (int nt = 0; nt < 8; ++nt) {
        float2 v0 = {oc[nt][0]*inv0, oc[nt][1]*inv0};
        float2 v1 = {oc[nt][2]*inv1, oc[nt][3]*inv1};
        *(float2*)&ob[base0 + nt*8 + cq] = v0;
        *(float2*)&ob[base1 + nt*8 + cq] = v1;
    }
}

// ---------------- launch ----------------------------------------------------
extern "C" void kernel_launch(void* const* d_in, const int* in_sizes, int n_in,
                              void* d_out, int out_size) {
    const float* q    = (const float*)d_in[0];
    const unsigned char* mask = (const unsigned char*)d_in[1];
    const float* Wq   = (const float*)d_in[2];
    const float* bq   = (const float*)d_in[3];
    const float* Wk   = (const float*)d_in[4];
    const float* bk   = (const float*)d_in[5];
    const float* Wv   = (const float*)d_in[6];
    const float* bv   = (const float*)d_in[7];
    const float* Wo   = (const float*)d_in[8];
    const float* bo   = (const float*)d_in[9];
    float* out = (float*)d_out;

    float *qh, *kh, *vh, *obuf;
    cudaGetSymbolAddress((void**)&qh, g_qh);
    cudaGetSymbolAddress((void**)&kh, g_kh);
    cudaGetSymbolAddress((void**)&vh, g_vh);
    cudaGetSymbolAddress((void**)&obuf, g_ob);

    detect_mask_kernel<<<1, 256>>>(mask);
    convert_mask_kernel<<<(BATCH*SEQ + 255) / 256, 256>>>(mask);

    const int gemm_smem = 4 * 128 * GST * 2;          // 40960 B
    const int attn_smem = 6 * 64 * AST * 2 + 64 * 4;  // 55552 B
    static bool attr_done = false;
    if (!attr_done) {
        cudaFuncSetAttribute(gemm3_kernel<true>,
                             cudaFuncAttributeMaxDynamicSharedMemorySize, gemm_smem);
        cudaFuncSetAttribute(gemm3_kernel<false>,
                             cudaFuncAttributeMaxDynamicSharedMemorySize, gemm_smem);
        cudaFuncSetAttribute(attn_mma_kernel,
                             cudaFuncAttributeMaxDynamicSharedMemorySize, attn_smem);
        attr_done = true;
    }

    dim3 gg(DMODEL / 128, MROWS / 128);   // (8, 64)
    gemm3_kernel<true><<<gg, 256, gemm_smem>>>(q, Wq, bq, qh);
    gemm3_kernel<true><<<gg, 256, gemm_smem>>>(q, Wk, bk, kh);
    gemm3_kernel<true><<<gg, 256, gemm_smem>>>(q, Wv, bv, vh);

    attn_mma_kernel<<<dim3(SEQ / 64, BATCH * NHEAD), 128, attn_smem>>>(qh, kh, vh, obuf);

    gemm3_kernel<false><<<gg, 256, gemm_smem>>>(obuf, Wo, bo, out);
}